// round 14
// baseline (speedup 1.0000x reference)
#include <cuda_runtime.h>
#include <cstdint>

// ---------------- problem constants ----------------
#define NROWS   262144
#define DDIM    128
#define TILE_M  128
#define NTILES  (NROWS / TILE_M)        // 2048
#define GRID_MAIN 148
#define P1_BLOCKS 1024
#define P1_ROWS (NROWS / P1_BLOCKS)     // 256

#define APAD 132                        // floats per padded A row (conflict-free frag loads)
#define ABUF_FLOATS (TILE_M * APAD)     // 16896
#define SB_FLOATS   (16 * 16 * 32 * 2)  // 16384 (B fragments, pre-permuted tf32)
#define DSMEM_BYTES ((2 * ABUF_FLOATS + SB_FLOATS) * 4)   // 200704

// ---------------- device scratch (no allocs allowed) ----------------
__device__ float g_part[P1_BLOCKS * 2 * 128];
__device__ int   g_cnt[P1_BLOCKS * 2];
__device__ float g_bias[128];
__device__ int   g_masktype;            // 0=int32, 1=byte, 2=float
__device__ float g_Bperm[SB_FLOATS];    // tf32 bits of W1a, [kk][nb][lane][2]

// ---------------- small helpers ----------------
__device__ __forceinline__ uint32_t smem_u32(const void* p) {
    uint32_t r;
    asm("{ .reg .u64 t; cvta.to.shared.u64 t, %1; cvt.u32.u64 %0, t; }" : "=r"(r) : "l"(p));
    return r;
}

__device__ __forceinline__ void cp16(uint32_t dst, const void* src) {
    asm volatile("cp.async.cg.shared.global [%0], [%1], 16;" :: "r"(dst), "l"(src));
}

__device__ __forceinline__ bool rdmask(const void* m, int i, int mt) {
    if (mt == 1) return ((const unsigned char*)m)[i] != 0;
    if (mt == 2) return ((const float*)m)[i] != 0.0f;
    return ((const int*)m)[i] != 0;
}

__device__ __forceinline__ uint32_t f2tf32(float f) {
    uint32_t r;
    asm("cvt.rna.tf32.f32 %0, %1;" : "=r"(r) : "f"(f));
    return r;
}

__device__ __forceinline__ void mma_tf32(float* d, uint32_t a0, uint32_t a1,
                                         uint32_t a2, uint32_t a3,
                                         uint32_t b0, uint32_t b1) {
    asm volatile(
        "mma.sync.aligned.m16n8k8.row.col.f32.tf32.tf32.f32 "
        "{%0,%1,%2,%3}, {%4,%5,%6,%7}, {%8,%9}, {%0,%1,%2,%3};\n"
        : "+f"(d[0]), "+f"(d[1]), "+f"(d[2]), "+f"(d[3])
        : "r"(a0), "r"(a1), "r"(a2), "r"(a3), "r"(b0), "r"(b1));
}

// ---------------- kernel 0: sniff mask dtype ----------------
__global__ void sniff_kernel(const int* m) {
    int v = m[0];
    g_masktype = (v == 0x01010101) ? 1 : ((v == 0x3F800000) ? 2 : 0);
}

// ---------------- kernel 1: per-block masked partial sums ----------------
__global__ void __launch_bounds__(128) pool1_kernel(const float* __restrict__ h,
                                                    const int* __restrict__ types,
                                                    const void* __restrict__ masks) {
    const int t = threadIdx.x;
    const int base = blockIdx.x * P1_ROWS;
    const int mt = g_masktype;
    float sl = 0.f, ss = 0.f;
    int cl = 0, cs = 0;
#pragma unroll 4
    for (int r = 0; r < P1_ROWS; r++) {
        const int i = base + r;
        const int ty = __ldg(types + i);
        const bool mk = rdmask(masks, i, mt);
        const float v = __ldg(h + (size_t)i * DDIM + t);
        const bool L = (ty == 1) && mk;
        const bool S = (ty == 2) && mk;
        sl += L ? v : 0.f;
        ss += S ? v : 0.f;
        cl += L; cs += S;
    }
    g_part[(blockIdx.x * 2 + 0) * 128 + t] = sl;
    g_part[(blockIdx.x * 2 + 1) * 128 + t] = ss;
    if (t == 0) { g_cnt[blockIdx.x * 2 + 0] = cl; g_cnt[blockIdx.x * 2 + 1] = cs; }
}

// ---------------- kernel 2: reduce + fold pooled means into bias_eff ----------------
__global__ void __launch_bounds__(512) pool2_kernel(const float* __restrict__ W1,
                                                    const float* __restrict__ b1) {
    __shared__ float s_sl[4][128], s_ss[4][128];
    __shared__ float s_hl[128], s_hs[128];
    __shared__ int s_cl, s_cs;
    const int t = threadIdx.x;
    const int col = t & 127, p = t >> 7;
    float sl = 0.f, ss = 0.f;
#pragma unroll 4
    for (int g = p * 256; g < p * 256 + 256; ++g) {
        sl += g_part[(g * 2 + 0) * 128 + col];
        ss += g_part[(g * 2 + 1) * 128 + col];
    }
    s_sl[p][col] = sl;
    s_ss[p][col] = ss;
    if (t < 32) {
        int cl = 0, cs = 0;
        for (int g = t; g < P1_BLOCKS; g += 32) { cl += g_cnt[g * 2]; cs += g_cnt[g * 2 + 1]; }
#pragma unroll
        for (int o = 16; o > 0; o >>= 1) {
            cl += __shfl_down_sync(0xFFFFFFFFu, cl, o);
            cs += __shfl_down_sync(0xFFFFFFFFu, cs, o);
        }
        if (t == 0) { s_cl = cl; s_cs = cs; }
    }
    __syncthreads();
    if (t < 128) {
        float SL = s_sl[0][t] + s_sl[1][t] + s_sl[2][t] + s_sl[3][t];
        float SS = s_ss[0][t] + s_ss[1][t] + s_ss[2][t] + s_ss[3][t];
        s_hl[t] = (s_cl > 0) ? SL / (float)s_cl : 0.f;
        s_hs[t] = (s_cs > 0) ? SS / (float)s_cs : 0.f;
    }
    __syncthreads();
    if (t < 128) {
        float acc = b1[t];
        const float* w = W1 + (size_t)t * 384;
#pragma unroll 8
        for (int k = 0; k < 128; k++)
            acc += w[128 + k] * s_hl[k] + w[256 + k] * s_hs[k];
        g_bias[t] = acc;
    }
}

// ---------------- kernel 2b: pre-permute + tf32-convert W1a into B-fragment layout ----
// B[k][n] = W1[n*384 + k]  (n = hid dim, k = input dim)
// g_Bperm index: ((kk*16 + nb)*32 + lane)*2 + e  with n = nb*8 + lane/4, k = kk*8 + lane%4 + 4e
__global__ void __launch_bounds__(256) setupB_kernel(const float* __restrict__ W1) {
    const int idx = blockIdx.x * 256 + threadIdx.x;   // 0 .. 16383
    const int e    = idx & 1;
    const int lane = (idx >> 1) & 31;
    const int nb   = (idx >> 6) & 15;
    const int kk   = idx >> 10;
    const int n = nb * 8 + (lane >> 2);
    const int k = kk * 8 + (lane & 3) + 4 * e;
    const uint32_t bits = f2tf32(__ldg(W1 + (size_t)n * 384 + k));
    g_Bperm[((kk * 16 + nb) * 32 + lane) * 2 + e] = __uint_as_float(bits);
}

// ---------------- kernel 3: persistent tf32 mma.sync GEMM + fused epilogue --------
__global__ void __launch_bounds__(256, 1)
main_kernel(const float* __restrict__ h, const int* __restrict__ types,
            const void* __restrict__ masks, const int* __restrict__ rid,
            const float* __restrict__ W2, const float* __restrict__ b2,
            const float* __restrict__ rtab, float* __restrict__ out) {
    extern __shared__ float sm[];
    float* sB = sm + 2 * ABUF_FLOATS;
    __shared__ float s_bias[128], s_w2[128];
    __shared__ __align__(16) float s_rule[128];
    __shared__ float s_bb[128], s_rr[128];
    __shared__ float s_b2;

    const int tid  = threadIdx.x;
    const int warp = tid >> 5;
    const int lane = tid & 31;
    const int mt   = g_masktype;
    const uint32_t sAaddr = smem_u32(sm);
    const uint32_t sBaddr = smem_u32(sB);

    if (tid < 128) {
        s_bias[tid] = g_bias[tid];
        s_w2[tid]   = __ldg(W2 + tid);
        const int rv = rid ? __ldg(rid) : 0;
        s_rule[tid] = __ldg(rtab + (size_t)rv * 128 + tid);
    }
    if (tid == 0) s_b2 = __ldg(b2);

    // prologue: cp.async B fragments + first A tile
#pragma unroll
    for (int i = 0; i < 16; i++) {
        const int q = i * 256 + tid;                 // 0..4095 float4 quads
        cp16(sBaddr + q * 16, g_Bperm + q * 4);
    }
    {
        const float* src = h + (size_t)blockIdx.x * TILE_M * DDIM;
#pragma unroll
        for (int i = 0; i < 16; i++) {
            const int idx = i * 256 + tid;
            const int row = idx >> 5, q = idx & 31;
            cp16(sAaddr + row * (APAD * 4) + q * 16, src + row * DDIM + q * 4);
        }
    }
    asm volatile("cp.async.commit_group;");

    int buf = 0;
    for (int tile = blockIdx.x; tile < NTILES; tile += GRID_MAIN) {
        asm volatile("cp.async.wait_group 0;" ::: "memory");
        __syncthreads();

        // prefetch next tile into the other buffer
        const int ntile = tile + GRID_MAIN;
        if (ntile < NTILES) {
            const uint32_t dst = sAaddr + (buf ^ 1) * (ABUF_FLOATS * 4);
            const float* src = h + (size_t)ntile * TILE_M * DDIM;
#pragma unroll
            for (int i = 0; i < 16; i++) {
                const int idx = i * 256 + tid;
                const int row = idx >> 5, q = idx & 31;
                cp16(dst + row * (APAD * 4) + q * 16, src + row * DDIM + q * 4);
            }
        }
        asm volatile("cp.async.commit_group;");

        // ---- GEMM: warp owns rows [warp*16, warp*16+16), all 128 hid cols ----
        const float* A = sm + buf * ABUF_FLOATS;
        const int g  = lane >> 2;       // 0..7
        const int c4 = lane & 3;        // 0..3
        const float* a_base = A + (warp * 16 + g) * APAD + c4;

        float acc[64];
#pragma unroll
        for (int i = 0; i < 64; i++) acc[i] = 0.f;

#pragma unroll 2
        for (int kk = 0; kk < 16; kk++) {
            const float* ap = a_base + kk * 8;
            const uint32_t a0 = f2tf32(ap[0]);
            const uint32_t a1 = f2tf32(ap[8 * APAD]);
            const uint32_t a2 = f2tf32(ap[4]);
            const uint32_t a3 = f2tf32(ap[8 * APAD + 4]);
            const float* bp = sB + (kk * 16) * 64 + lane * 2;
#pragma unroll
            for (int nb = 0; nb < 16; nb++) {
                const float2 bv = *(const float2*)(bp + nb * 64);
                mma_tf32(acc + nb * 4, a0, a1, a2, a3,
                         __float_as_uint(bv.x), __float_as_uint(bv.y));
            }
        }

        // ---- epilogue 1: beta per row (hid never materialized) ----
        float s0 = 0.f, s1 = 0.f;
#pragma unroll
        for (int nb = 0; nb < 16; nb++) {
            const int col0 = nb * 8 + 2 * c4;
            const float w0 = s_w2[col0], w1 = s_w2[col0 + 1];
            const float bb0 = s_bias[col0], bb1 = s_bias[col0 + 1];
            s0 = fmaf(fmaxf(acc[nb * 4 + 0] + bb0, 0.f), w0,
                 fmaf(fmaxf(acc[nb * 4 + 1] + bb1, 0.f), w1, s0));
            s1 = fmaf(fmaxf(acc[nb * 4 + 2] + bb0, 0.f), w0,
                 fmaf(fmaxf(acc[nb * 4 + 3] + bb1, 0.f), w1, s1));
        }
        s0 += __shfl_xor_sync(0xFFFFFFFFu, s0, 1);
        s0 += __shfl_xor_sync(0xFFFFFFFFu, s0, 2);
        s1 += __shfl_xor_sync(0xFFFFFFFFu, s1, 1);
        s1 += __shfl_xor_sync(0xFFFFFFFFu, s1, 2);

        if (c4 == 0) {
#pragma unroll
            for (int half = 0; half < 2; half++) {
                const int r = warp * 16 + g + half * 8;
                const float logit = (half ? s1 : s0) + s_b2;
                const float beta = 1.f / (1.f + __expf(-logit));
                const int grow = tile * TILE_M + r;
                const int ty = __ldg(types + grow);
                const bool car = (ty == 0) && rdmask(masks, grow, mt);
                out[(size_t)NROWS * DDIM + grow] = car ? beta : 0.f;
                s_bb[r] = car ? beta : 1.f;
                s_rr[r] = car ? (1.f - beta) : 0.f;
            }
        }
        __syncthreads();

        // ---- epilogue 2: blend from SMEM A tile (exact fp32 h), coalesced stores ----
#pragma unroll
        for (int j = 0; j < 16; j++) {
            const int idx = j * 256 + tid;
            const int row = idx >> 5, q = idx & 31;
            const float4 a = *(const float4*)(A + row * APAD + q * 4);
            const float4 rv = *(const float4*)(s_rule + q * 4);
            const float bbv = s_bb[row], rrv = s_rr[row];
            float4 o;
            o.x = fmaf(bbv, a.x, rrv * rv.x);
            o.y = fmaf(bbv, a.y, rrv * rv.y);
            o.z = fmaf(bbv, a.z, rrv * rv.z);
            o.w = fmaf(bbv, a.w, rrv * rv.w);
            *(float4*)(out + ((size_t)(tile * TILE_M + row)) * DDIM + q * 4) = o;
        }

        buf ^= 1;
    }
}

// ---------------- launch ----------------
extern "C" void kernel_launch(void* const* d_in, const int* in_sizes, int n_in,
                              void* d_out, int out_size) {
    const float* h;
    const int*   types;
    const void*  masks;
    const int*   rid;
    const float* W1; const float* b1; const float* W2; const float* b2; const float* rtab;

    if (n_in >= 9) {
        h = (const float*)d_in[0]; types = (const int*)d_in[1]; masks = d_in[2];
        rid = (const int*)d_in[3];
        W1 = (const float*)d_in[4]; b1 = (const float*)d_in[5];
        W2 = (const float*)d_in[6]; b2 = (const float*)d_in[7];
        rtab = (const float*)d_in[8];
    } else {  // rule_id omitted by harness
        h = (const float*)d_in[0]; types = (const int*)d_in[1]; masks = d_in[2];
        rid = nullptr;
        W1 = (const float*)d_in[3]; b1 = (const float*)d_in[4];
        W2 = (const float*)d_in[5]; b2 = (const float*)d_in[6];
        rtab = (const float*)d_in[7];
    }
    float* out = (float*)d_out;

    sniff_kernel<<<1, 1>>>((const int*)masks);
    pool1_kernel<<<P1_BLOCKS, 128>>>(h, types, masks);
    pool2_kernel<<<1, 512>>>(W1, b1);
    setupB_kernel<<<SB_FLOATS / 256, 256>>>(W1);
    cudaFuncSetAttribute(main_kernel, cudaFuncAttributeMaxDynamicSharedMemorySize, DSMEM_BYTES);
    main_kernel<<<GRID_MAIN, 256, DSMEM_BYTES>>>(h, types, masks, rid, W2, b2, rtab, out);
}

// round 15
// speedup vs baseline: 1.0684x; 1.0684x over previous
#include <cuda_runtime.h>
#include <cstdint>

// ---------------- problem constants ----------------
#define NROWS   262144
#define DDIM    128
#define TILE_M  128
#define NTILES  (NROWS / TILE_M)        // 2048
#define GRID_MAIN 148
#define P1_BLOCKS 1024
#define P1_ROWS (NROWS / P1_BLOCKS)     // 256

#define APAD 132                        // floats per padded A row
#define ABUF_FLOATS (TILE_M * APAD)     // 16896
#define SB_U32   (8 * 16 * 32 * 2)      // 8192 u32: B fp16 fragments [kk][nblk][lane][e]
#define DSMEM_BYTES (2 * ABUF_FLOATS * 4 + SB_U32 * 4)   // 135168 + 32768 = 167936

// ---------------- device scratch (no allocs allowed) ----------------
__device__ float    g_part[P1_BLOCKS * 2 * 128];
__device__ int      g_cnt[P1_BLOCKS * 2];
__device__ float    g_bias[128];
__device__ uint32_t g_Bperm[SB_U32];

// ---------------- small helpers ----------------
__device__ __forceinline__ uint32_t smem_u32(const void* p) {
    uint32_t r;
    asm("{ .reg .u64 t; cvta.to.shared.u64 t, %1; cvt.u32.u64 %0, t; }" : "=r"(r) : "l"(p));
    return r;
}

__device__ __forceinline__ void cp16(uint32_t dst, const void* src) {
    asm volatile("cp.async.cg.shared.global [%0], [%1], 16;" :: "r"(dst), "l"(src));
}

__device__ __forceinline__ int sniff_mt(const void* m) {
    const int v = *(const int*)m;
    return (v == 0x01010101) ? 1 : ((v == 0x3F800000) ? 2 : 0);
}

__device__ __forceinline__ bool rdmask(const void* m, int i, int mt) {
    if (mt == 1) return ((const unsigned char*)m)[i] != 0;
    if (mt == 2) return ((const float*)m)[i] != 0.0f;
    return ((const int*)m)[i] != 0;
}

// pack two f32 -> f16x2 (lo = first arg)
__device__ __forceinline__ uint32_t pack_h2(float lo, float hi) {
    uint32_t r;
    asm("cvt.rn.f16x2.f32 %0, %1, %2;" : "=r"(r) : "f"(hi), "f"(lo));
    return r;
}

__device__ __forceinline__ void mma_fp16(float* d, uint32_t a0, uint32_t a1,
                                         uint32_t a2, uint32_t a3,
                                         uint32_t b0, uint32_t b1) {
    asm volatile(
        "mma.sync.aligned.m16n8k16.row.col.f32.f16.f16.f32 "
        "{%0,%1,%2,%3}, {%4,%5,%6,%7}, {%8,%9}, {%0,%1,%2,%3};\n"
        : "+f"(d[0]), "+f"(d[1]), "+f"(d[2]), "+f"(d[3])
        : "r"(a0), "r"(a1), "r"(a2), "r"(a3), "r"(b0), "r"(b1));
}

// ---------------- kernel 1: per-block masked partial sums ----------------
__global__ void __launch_bounds__(128) pool1_kernel(const float* __restrict__ h,
                                                    const int* __restrict__ types,
                                                    const void* __restrict__ masks) {
    const int t = threadIdx.x;
    const int base = blockIdx.x * P1_ROWS;
    const int mt = sniff_mt(masks);
    float sl = 0.f, ss = 0.f;
    int cl = 0, cs = 0;
#pragma unroll 4
    for (int r = 0; r < P1_ROWS; r++) {
        const int i = base + r;
        const int ty = __ldg(types + i);
        const bool mk = rdmask(masks, i, mt);
        const float v = __ldg(h + (size_t)i * DDIM + t);
        const bool L = (ty == 1) && mk;
        const bool S = (ty == 2) && mk;
        sl += L ? v : 0.f;
        ss += S ? v : 0.f;
        cl += L; cs += S;
    }
    g_part[(blockIdx.x * 2 + 0) * 128 + t] = sl;
    g_part[(blockIdx.x * 2 + 1) * 128 + t] = ss;
    if (t == 0) { g_cnt[blockIdx.x * 2 + 0] = cl; g_cnt[blockIdx.x * 2 + 1] = cs; }
}

// ---------------- kernel 2 (fused): block 0 = pool2 reduce+bias fold;
//                  blocks 1..16 = pre-permute W1a into fp16 B fragments ----------------
// B fragment (m16n8k16 row.col): n = nblk*8 + lane/4, k = kk*16 + 2*(lane%4) + 8*e (+h)
__global__ void __launch_bounds__(512) setup_kernel(const float* __restrict__ W1,
                                                    const float* __restrict__ b1) {
    const int t = threadIdx.x;
    if (blockIdx.x > 0) {
        const int idx = (blockIdx.x - 1) * 512 + t;     // 0 .. 8191
        const int e    = idx & 1;
        const int lane = (idx >> 1) & 31;
        const int nblk = (idx >> 6) & 15;
        const int kk   = idx >> 10;                     // 0..7
        const int n = nblk * 8 + (lane >> 2);
        const int k = kk * 16 + 2 * (lane & 3) + 8 * e;
        const float v0 = __ldg(W1 + (size_t)n * 384 + k);
        const float v1 = __ldg(W1 + (size_t)n * 384 + k + 1);
        g_Bperm[idx] = pack_h2(v0, v1);
        return;
    }
    // ----- block 0: pool2 -----
    __shared__ float s_sl[4][128], s_ss[4][128];
    __shared__ float s_hl[128], s_hs[128];
    __shared__ int s_cl, s_cs;
    const int col = t & 127, p = t >> 7;
    float sl = 0.f, ss = 0.f;
#pragma unroll 4
    for (int g = p * 256; g < p * 256 + 256; ++g) {
        sl += g_part[(g * 2 + 0) * 128 + col];
        ss += g_part[(g * 2 + 1) * 128 + col];
    }
    s_sl[p][col] = sl;
    s_ss[p][col] = ss;
    if (t < 32) {
        int cl = 0, cs = 0;
        for (int g = t; g < P1_BLOCKS; g += 32) { cl += g_cnt[g * 2]; cs += g_cnt[g * 2 + 1]; }
#pragma unroll
        for (int o = 16; o > 0; o >>= 1) {
            cl += __shfl_down_sync(0xFFFFFFFFu, cl, o);
            cs += __shfl_down_sync(0xFFFFFFFFu, cs, o);
        }
        if (t == 0) { s_cl = cl; s_cs = cs; }
    }
    __syncthreads();
    if (t < 128) {
        float SL = s_sl[0][t] + s_sl[1][t] + s_sl[2][t] + s_sl[3][t];
        float SS = s_ss[0][t] + s_ss[1][t] + s_ss[2][t] + s_ss[3][t];
        s_hl[t] = (s_cl > 0) ? SL / (float)s_cl : 0.f;
        s_hs[t] = (s_cs > 0) ? SS / (float)s_cs : 0.f;
    }
    __syncthreads();
    if (t < 128) {
        float acc = b1[t];
        const float* w = W1 + (size_t)t * 384;
#pragma unroll 8
        for (int k = 0; k < 128; k++)
            acc += w[128 + k] * s_hl[k] + w[256 + k] * s_hs[k];
        g_bias[t] = acc;
    }
}

// ---------------- kernel 3: persistent fp16 mma.sync GEMM + fused epilogue --------
// 512 threads, 16 warps: warpRow = warp>>1 (16 rows), warpCol = warp&1 (64 cols)
__global__ void __launch_bounds__(512, 1)
main_kernel(const float* __restrict__ h, const int* __restrict__ types,
            const void* __restrict__ masks, const int* __restrict__ rid,
            const float* __restrict__ W2, const float* __restrict__ b2,
            const float* __restrict__ rtab, float* __restrict__ out) {
    extern __shared__ float sm[];
    uint32_t* sB = (uint32_t*)(sm + 2 * ABUF_FLOATS);
    __shared__ float s_bias[128], s_w2[128];
    __shared__ __align__(16) float s_rule[128];
    __shared__ float s_bb[128], s_rr[128];
    __shared__ float s_lpart[2][128];
    __shared__ float s_b2;

    const int tid  = threadIdx.x;
    const int warp = tid >> 5;
    const int lane = tid & 31;
    const int warpRow = warp >> 1;      // 0..7
    const int warpCol = warp & 1;       // 0..1
    const int g  = lane >> 2;           // 0..7
    const int t4 = lane & 3;            // 0..3
    const int mt = sniff_mt(masks);
    const uint32_t sAaddr = smem_u32(sm);
    const uint32_t sBaddr = smem_u32(sB);

    if (tid < 128) {
        s_bias[tid] = g_bias[tid];
        s_w2[tid]   = __ldg(W2 + tid);
        const int rv = rid ? __ldg(rid) : 0;
        s_rule[tid] = __ldg(rtab + (size_t)rv * 128 + tid);
    }
    if (tid == 0) s_b2 = __ldg(b2);

    // prologue: cp.async B fragments (32 KB) + first A tile
#pragma unroll
    for (int i = 0; i < 4; i++) {
        const int q = i * 512 + tid;                 // 0..2047 16B quads
        cp16(sBaddr + q * 16, g_Bperm + q * 4);
    }
    {
        const float* src = h + (size_t)blockIdx.x * TILE_M * DDIM;
#pragma unroll
        for (int i = 0; i < 8; i++) {
            const int idx = i * 512 + tid;
            const int row = idx >> 5, q = idx & 31;
            cp16(sAaddr + row * (APAD * 4) + q * 16, src + row * DDIM + q * 4);
        }
    }
    asm volatile("cp.async.commit_group;");

    int buf = 0;
    for (int tile = blockIdx.x; tile < NTILES; tile += GRID_MAIN) {
        asm volatile("cp.async.wait_group 0;" ::: "memory");
        __syncthreads();

        // prefetch next tile into the other buffer
        const int ntile = tile + GRID_MAIN;
        if (ntile < NTILES) {
            const uint32_t dst = sAaddr + (buf ^ 1) * (ABUF_FLOATS * 4);
            const float* src = h + (size_t)ntile * TILE_M * DDIM;
#pragma unroll
            for (int i = 0; i < 8; i++) {
                const int idx = i * 512 + tid;
                const int row = idx >> 5, q = idx & 31;
                cp16(dst + row * (APAD * 4) + q * 16, src + row * DDIM + q * 4);
            }
        }
        asm volatile("cp.async.commit_group;");

        // ---- GEMM: warp owns rows [warpRow*16, +16), cols [warpCol*64, +64) ----
        const float* A = sm + buf * ABUF_FLOATS;
        const float* a0p = A + (warpRow * 16 + g) * APAD + 2 * t4;
        const float* a1p = a0p + 8 * APAD;

        float acc[32];
#pragma unroll
        for (int i = 0; i < 32; i++) acc[i] = 0.f;

#pragma unroll
        for (int kk = 0; kk < 8; kk++) {
            const float2 f0 = *(const float2*)(a0p + kk * 16);
            const float2 f1 = *(const float2*)(a1p + kk * 16);
            const float2 f2 = *(const float2*)(a0p + kk * 16 + 8);
            const float2 f3 = *(const float2*)(a1p + kk * 16 + 8);
            const uint32_t A0 = pack_h2(f0.x, f0.y);
            const uint32_t A1 = pack_h2(f1.x, f1.y);
            const uint32_t A2 = pack_h2(f2.x, f2.y);
            const uint32_t A3 = pack_h2(f3.x, f3.y);
            const uint32_t* bp = sB + ((kk * 16 + warpCol * 8) * 32 + lane) * 2;
#pragma unroll
            for (int nb = 0; nb < 8; nb++) {
                const uint32_t b0 = bp[nb * 64];
                const uint32_t b1 = bp[nb * 64 + 1];
                mma_fp16(acc + nb * 4, A0, A1, A2, A3, b0, b1);
            }
        }

        // ---- epilogue 1: partial beta dot over this warp's 64 cols ----
        float s0 = 0.f, s1 = 0.f;
#pragma unroll
        for (int nb = 0; nb < 8; nb++) {
            const int col0 = warpCol * 64 + nb * 8 + 2 * t4;
            const float w0 = s_w2[col0], w1 = s_w2[col0 + 1];
            const float bb0 = s_bias[col0], bb1 = s_bias[col0 + 1];
            s0 = fmaf(fmaxf(acc[nb * 4 + 0] + bb0, 0.f), w0,
                 fmaf(fmaxf(acc[nb * 4 + 1] + bb1, 0.f), w1, s0));
            s1 = fmaf(fmaxf(acc[nb * 4 + 2] + bb0, 0.f), w0,
                 fmaf(fmaxf(acc[nb * 4 + 3] + bb1, 0.f), w1, s1));
        }
        s0 += __shfl_xor_sync(0xFFFFFFFFu, s0, 1);
        s0 += __shfl_xor_sync(0xFFFFFFFFu, s0, 2);
        s1 += __shfl_xor_sync(0xFFFFFFFFu, s1, 1);
        s1 += __shfl_xor_sync(0xFFFFFFFFu, s1, 2);
        if (t4 == 0) {
            s_lpart[warpCol][warpRow * 16 + g]     = s0;
            s_lpart[warpCol][warpRow * 16 + g + 8] = s1;
        }
        __syncthreads();

        if (tid < 128) {
            const float logit = s_lpart[0][tid] + s_lpart[1][tid] + s_b2;
            const float beta = 1.f / (1.f + __expf(-logit));
            const int grow = tile * TILE_M + tid;
            const int ty = __ldg(types + grow);
            const bool car = (ty == 0) && rdmask(masks, grow, mt);
            out[(size_t)NROWS * DDIM + grow] = car ? beta : 0.f;
            s_bb[tid] = car ? beta : 1.f;
            s_rr[tid] = car ? (1.f - beta) : 0.f;
        }
        __syncthreads();

        // ---- epilogue 2: blend from SMEM A tile (exact fp32 h), coalesced stores ----
#pragma unroll
        for (int j = 0; j < 8; j++) {
            const int idx = j * 512 + tid;
            const int row = idx >> 5, q = idx & 31;
            const float4 a = *(const float4*)(A + row * APAD + q * 4);
            const float4 rv = *(const float4*)(s_rule + q * 4);
            const float bbv = s_bb[row], rrv = s_rr[row];
            float4 o;
            o.x = fmaf(bbv, a.x, rrv * rv.x);
            o.y = fmaf(bbv, a.y, rrv * rv.y);
            o.z = fmaf(bbv, a.z, rrv * rv.z);
            o.w = fmaf(bbv, a.w, rrv * rv.w);
            *(float4*)(out + ((size_t)(tile * TILE_M + row)) * DDIM + q * 4) = o;
        }

        buf ^= 1;
    }
}

// ---------------- launch ----------------
extern "C" void kernel_launch(void* const* d_in, const int* in_sizes, int n_in,
                              void* d_out, int out_size) {
    const float* h;
    const int*   types;
    const void*  masks;
    const int*   rid;
    const float* W1; const float* b1; const float* W2; const float* b2; const float* rtab;

    if (n_in >= 9) {
        h = (const float*)d_in[0]; types = (const int*)d_in[1]; masks = d_in[2];
        rid = (const int*)d_in[3];
        W1 = (const float*)d_in[4]; b1 = (const float*)d_in[5];
        W2 = (const float*)d_in[6]; b2 = (const float*)d_in[7];
        rtab = (const float*)d_in[8];
    } else {  // rule_id omitted by harness
        h = (const float*)d_in[0]; types = (const int*)d_in[1]; masks = d_in[2];
        rid = nullptr;
        W1 = (const float*)d_in[3]; b1 = (const float*)d_in[4];
        W2 = (const float*)d_in[5]; b2 = (const float*)d_in[6];
        rtab = (const float*)d_in[7];
    }
    float* out = (float*)d_out;

    pool1_kernel<<<P1_BLOCKS, 128>>>(h, types, masks);
    setup_kernel<<<17, 512>>>(W1, b1);
    cudaFuncSetAttribute(main_kernel, cudaFuncAttributeMaxDynamicSharedMemorySize, DSMEM_BYTES);
    main_kernel<<<GRID_MAIN, 512, DSMEM_BYTES>>>(h, types, masks, rid, W2, b2, rtab, out);
}

// round 16
// speedup vs baseline: 1.9122x; 1.7898x over previous
#include <cuda_runtime.h>
#include <cstdint>

// ---------------- problem constants ----------------
#define NROWS   262144
#define DDIM    128
#define TILE_M  128
#define NTILES  (NROWS / TILE_M)        // 2048
#define GRID_MAIN 148
#define P1_BLOCKS 512
#define P1_RPB  (NROWS / P1_BLOCKS)     // 512 rows per block (16 warps x 32 rows)

#define APAD 132                        // floats per padded A row
#define ABUF_FLOATS (TILE_M * APAD)     // 16896
#define SB_U32   (8 * 16 * 32 * 2)      // 8192 u32: B fp16 fragments [kk][nblk][lane][e]
#define DSMEM_BYTES (2 * ABUF_FLOATS * 4 + SB_U32 * 4)   // 167936

// ---------------- device scratch (no allocs allowed) ----------------
__device__ float    g_part[P1_BLOCKS * 2 * 128];
__device__ int      g_cnt[P1_BLOCKS * 2];
__device__ float    g_bias[128];
__device__ uint32_t g_Bperm[SB_U32];

// ---------------- small helpers ----------------
__device__ __forceinline__ uint32_t smem_u32(const void* p) {
    uint32_t r;
    asm("{ .reg .u64 t; cvta.to.shared.u64 t, %1; cvt.u32.u64 %0, t; }" : "=r"(r) : "l"(p));
    return r;
}

__device__ __forceinline__ void cp16(uint32_t dst, const void* src) {
    asm volatile("cp.async.cg.shared.global [%0], [%1], 16;" :: "r"(dst), "l"(src));
}

__device__ __forceinline__ int sniff_mt(const void* m) {
    const int v = *(const int*)m;
    return (v == 0x01010101) ? 1 : ((v == 0x3F800000) ? 2 : 0);
}

__device__ __forceinline__ bool rdmask(const void* m, int i, int mt) {
    if (mt == 1) return ((const unsigned char*)m)[i] != 0;
    if (mt == 2) return ((const float*)m)[i] != 0.0f;
    return ((const int*)m)[i] != 0;
}

// pack two f32 -> f16x2 (lo = first arg)
__device__ __forceinline__ uint32_t pack_h2(float lo, float hi) {
    uint32_t r;
    asm("cvt.rn.f16x2.f32 %0, %1, %2;" : "=r"(r) : "f"(hi), "f"(lo));
    return r;
}

__device__ __forceinline__ void mma_fp16(float* d, uint32_t a0, uint32_t a1,
                                         uint32_t a2, uint32_t a3,
                                         uint32_t b0, uint32_t b1) {
    asm volatile(
        "mma.sync.aligned.m16n8k16.row.col.f32.f16.f16.f32 "
        "{%0,%1,%2,%3}, {%4,%5,%6,%7}, {%8,%9}, {%0,%1,%2,%3};\n"
        : "+f"(d[0]), "+f"(d[1]), "+f"(d[2]), "+f"(d[3])
        : "r"(a0), "r"(a1), "r"(a2), "r"(a3), "r"(b0), "r"(b1));
}

// ---------------- kernel 1: warp-per-row masked partial sums ----------------
// 512 threads = 16 warps; warp handles 32 consecutive rows; lane owns 4 columns.
// Rows with type==0 or mask==0 are skipped entirely (no h load) - warp-uniform branch.
__global__ void __launch_bounds__(512) pool1_kernel(const float* __restrict__ h,
                                                    const int* __restrict__ types,
                                                    const void* __restrict__ masks) {
    __shared__ float s_red[2][16][128];
    __shared__ int   s_cnt[2][16];
    const int tid = threadIdx.x;
    const int warp = tid >> 5, lane = tid & 31;
    const int mt = sniff_mt(masks);
    const int rbase = blockIdx.x * P1_RPB + warp * 32;

    float4 sl = make_float4(0.f, 0.f, 0.f, 0.f);
    float4 ss = make_float4(0.f, 0.f, 0.f, 0.f);
    int cl = 0, cs = 0;

#pragma unroll
    for (int j = 0; j < 32; j += 4) {
        const int i0 = rbase + j;
        const int4 ty4 = *(const int4*)(types + i0);
        int tys[4] = {ty4.x, ty4.y, ty4.z, ty4.w};
        bool ms[4];
        if (mt == 1) {
            const uchar4 mv = *(const uchar4*)((const unsigned char*)masks + i0);
            ms[0] = mv.x != 0; ms[1] = mv.y != 0; ms[2] = mv.z != 0; ms[3] = mv.w != 0;
        } else if (mt == 2) {
            const float4 mv = *(const float4*)((const float*)masks + i0);
            ms[0] = mv.x != 0.f; ms[1] = mv.y != 0.f; ms[2] = mv.z != 0.f; ms[3] = mv.w != 0.f;
        } else {
            const int4 mv = *(const int4*)((const int*)masks + i0);
            ms[0] = mv.x != 0; ms[1] = mv.y != 0; ms[2] = mv.z != 0; ms[3] = mv.w != 0;
        }
#pragma unroll
        for (int u = 0; u < 4; u++) {
            const int ty = tys[u];
            if (ms[u] && ty != 0) {
                const float4 v = *(const float4*)(h + (size_t)(i0 + u) * DDIM + lane * 4);
                if (ty == 1) {
                    sl.x += v.x; sl.y += v.y; sl.z += v.z; sl.w += v.w; cl++;
                } else {
                    ss.x += v.x; ss.y += v.y; ss.z += v.z; ss.w += v.w; cs++;
                }
            }
        }
    }

    *(float4*)&s_red[0][warp][lane * 4] = sl;
    *(float4*)&s_red[1][warp][lane * 4] = ss;
    if (lane == 0) { s_cnt[0][warp] = cl; s_cnt[1][warp] = cs; }
    __syncthreads();

    if (tid < 256) {
        const int which = tid >> 7, col = tid & 127;
        float acc = 0.f;
#pragma unroll
        for (int w = 0; w < 16; w++) acc += s_red[which][w][col];
        g_part[(blockIdx.x * 2 + which) * 128 + col] = acc;
    }
    if (tid < 2) {
        int c = 0;
#pragma unroll
        for (int w = 0; w < 16; w++) c += s_cnt[tid][w];
        g_cnt[blockIdx.x * 2 + tid] = c;
    }
}

// ---------------- kernel 2 (fused): block 0 = pool2 reduce+bias fold;
//                  blocks 1..16 = pre-permute W1a into fp16 B fragments ----------------
// B fragment (m16n8k16 row.col): n = nblk*8 + lane/4, k = kk*16 + 2*(lane%4) + 8*e (+h)
__global__ void __launch_bounds__(512) setup_kernel(const float* __restrict__ W1,
                                                    const float* __restrict__ b1) {
    const int t = threadIdx.x;
    if (blockIdx.x > 0) {
        const int idx = (blockIdx.x - 1) * 512 + t;     // 0 .. 8191
        const int e    = idx & 1;
        const int lane = (idx >> 1) & 31;
        const int nblk = (idx >> 6) & 15;
        const int kk   = idx >> 10;                     // 0..7
        const int n = nblk * 8 + (lane >> 2);
        const int k = kk * 16 + 2 * (lane & 3) + 8 * e;
        const float v0 = __ldg(W1 + (size_t)n * 384 + k);
        const float v1 = __ldg(W1 + (size_t)n * 384 + k + 1);
        g_Bperm[idx] = pack_h2(v0, v1);
        return;
    }
    // ----- block 0: pool2 -----
    __shared__ float s_sl[4][128], s_ss[4][128];
    __shared__ float s_hl[128], s_hs[128];
    __shared__ int s_cl, s_cs;
    const int col = t & 127, p = t >> 7;
    float sl = 0.f, ss = 0.f;
#pragma unroll 4
    for (int g = p * (P1_BLOCKS / 4); g < (p + 1) * (P1_BLOCKS / 4); ++g) {
        sl += g_part[(g * 2 + 0) * 128 + col];
        ss += g_part[(g * 2 + 1) * 128 + col];
    }
    s_sl[p][col] = sl;
    s_ss[p][col] = ss;
    if (t < 32) {
        int cl = 0, cs = 0;
        for (int g = t; g < P1_BLOCKS; g += 32) { cl += g_cnt[g * 2]; cs += g_cnt[g * 2 + 1]; }
#pragma unroll
        for (int o = 16; o > 0; o >>= 1) {
            cl += __shfl_down_sync(0xFFFFFFFFu, cl, o);
            cs += __shfl_down_sync(0xFFFFFFFFu, cs, o);
        }
        if (t == 0) { s_cl = cl; s_cs = cs; }
    }
    __syncthreads();
    if (t < 128) {
        float SL = s_sl[0][t] + s_sl[1][t] + s_sl[2][t] + s_sl[3][t];
        float SS = s_ss[0][t] + s_ss[1][t] + s_ss[2][t] + s_ss[3][t];
        s_hl[t] = (s_cl > 0) ? SL / (float)s_cl : 0.f;
        s_hs[t] = (s_cs > 0) ? SS / (float)s_cs : 0.f;
    }
    __syncthreads();
    if (t < 128) {
        float acc = b1[t];
        const float* w = W1 + (size_t)t * 384;
#pragma unroll 8
        for (int k = 0; k < 128; k++)
            acc += w[128 + k] * s_hl[k] + w[256 + k] * s_hs[k];
        g_bias[t] = acc;
    }
}

// ---------------- kernel 3: persistent fp16 mma.sync GEMM + fused epilogue --------
// 512 threads, 16 warps: warpRow = warp>>1 (16 rows), warpCol = warp&1 (64 cols)
__global__ void __launch_bounds__(512, 1)
main_kernel(const float* __restrict__ h, const int* __restrict__ types,
            const void* __restrict__ masks, const int* __restrict__ rid,
            const float* __restrict__ W2, const float* __restrict__ b2,
            const float* __restrict__ rtab, float* __restrict__ out) {
    extern __shared__ float sm[];
    uint32_t* sB = (uint32_t*)(sm + 2 * ABUF_FLOATS);
    __shared__ float s_bias[128], s_w2[128];
    __shared__ __align__(16) float s_rule[128];
    __shared__ float s_bb[128], s_rr[128];
    __shared__ float s_lpart[2][128];
    __shared__ float s_b2;

    const int tid  = threadIdx.x;
    const int warp = tid >> 5;
    const int lane = tid & 31;
    const int warpRow = warp >> 1;      // 0..7
    const int warpCol = warp & 1;       // 0..1
    const int g  = lane >> 2;           // 0..7
    const int t4 = lane & 3;            // 0..3
    const int mt = sniff_mt(masks);
    const uint32_t sAaddr = smem_u32(sm);
    const uint32_t sBaddr = smem_u32(sB);

    if (tid < 128) {
        s_bias[tid] = g_bias[tid];
        s_w2[tid]   = __ldg(W2 + tid);
        const int rv = rid ? __ldg(rid) : 0;
        s_rule[tid] = __ldg(rtab + (size_t)rv * 128 + tid);
    }
    if (tid == 0) s_b2 = __ldg(b2);

    // prologue: cp.async B fragments (32 KB) + first A tile
#pragma unroll
    for (int i = 0; i < 4; i++) {
        const int q = i * 512 + tid;                 // 0..2047 16B quads
        cp16(sBaddr + q * 16, g_Bperm + q * 4);
    }
    {
        const float* src = h + (size_t)blockIdx.x * TILE_M * DDIM;
#pragma unroll
        for (int i = 0; i < 8; i++) {
            const int idx = i * 512 + tid;
            const int row = idx >> 5, q = idx & 31;
            cp16(sAaddr + row * (APAD * 4) + q * 16, src + row * DDIM + q * 4);
        }
    }
    asm volatile("cp.async.commit_group;");

    int buf = 0;
    for (int tile = blockIdx.x; tile < NTILES; tile += GRID_MAIN) {
        asm volatile("cp.async.wait_group 0;" ::: "memory");
        __syncthreads();

        // prefetch next tile into the other buffer
        const int ntile = tile + GRID_MAIN;
        if (ntile < NTILES) {
            const uint32_t dst = sAaddr + (buf ^ 1) * (ABUF_FLOATS * 4);
            const float* src = h + (size_t)ntile * TILE_M * DDIM;
#pragma unroll
            for (int i = 0; i < 8; i++) {
                const int idx = i * 512 + tid;
                const int row = idx >> 5, q = idx & 31;
                cp16(dst + row * (APAD * 4) + q * 16, src + row * DDIM + q * 4);
            }
        }
        asm volatile("cp.async.commit_group;");

        // ---- GEMM: warp owns rows [warpRow*16, +16), cols [warpCol*64, +64) ----
        const float* A = sm + buf * ABUF_FLOATS;
        const float* a0p = A + (warpRow * 16 + g) * APAD + 2 * t4;
        const float* a1p = a0p + 8 * APAD;

        float acc[32];
#pragma unroll
        for (int i = 0; i < 32; i++) acc[i] = 0.f;

#pragma unroll
        for (int kk = 0; kk < 8; kk++) {
            const float2 f0 = *(const float2*)(a0p + kk * 16);
            const float2 f1 = *(const float2*)(a1p + kk * 16);
            const float2 f2 = *(const float2*)(a0p + kk * 16 + 8);
            const float2 f3 = *(const float2*)(a1p + kk * 16 + 8);
            const uint32_t A0 = pack_h2(f0.x, f0.y);
            const uint32_t A1 = pack_h2(f1.x, f1.y);
            const uint32_t A2 = pack_h2(f2.x, f2.y);
            const uint32_t A3 = pack_h2(f3.x, f3.y);
            const uint32_t* bp = sB + ((kk * 16 + warpCol * 8) * 32 + lane) * 2;
#pragma unroll
            for (int nb = 0; nb < 8; nb++) {
                const uint32_t b0 = bp[nb * 64];
                const uint32_t b1 = bp[nb * 64 + 1];
                mma_fp16(acc + nb * 4, A0, A1, A2, A3, b0, b1);
            }
        }

        // ---- epilogue 1: partial beta dot over this warp's 64 cols ----
        float s0 = 0.f, s1 = 0.f;
#pragma unroll
        for (int nb = 0; nb < 8; nb++) {
            const int col0 = warpCol * 64 + nb * 8 + 2 * t4;
            const float w0 = s_w2[col0], w1 = s_w2[col0 + 1];
            const float bb0 = s_bias[col0], bb1 = s_bias[col0 + 1];
            s0 = fmaf(fmaxf(acc[nb * 4 + 0] + bb0, 0.f), w0,
                 fmaf(fmaxf(acc[nb * 4 + 1] + bb1, 0.f), w1, s0));
            s1 = fmaf(fmaxf(acc[nb * 4 + 2] + bb0, 0.f), w0,
                 fmaf(fmaxf(acc[nb * 4 + 3] + bb1, 0.f), w1, s1));
        }
        s0 += __shfl_xor_sync(0xFFFFFFFFu, s0, 1);
        s0 += __shfl_xor_sync(0xFFFFFFFFu, s0, 2);
        s1 += __shfl_xor_sync(0xFFFFFFFFu, s1, 1);
        s1 += __shfl_xor_sync(0xFFFFFFFFu, s1, 2);
        if (t4 == 0) {
            s_lpart[warpCol][warpRow * 16 + g]     = s0;
            s_lpart[warpCol][warpRow * 16 + g + 8] = s1;
        }
        __syncthreads();

        if (tid < 128) {
            const float logit = s_lpart[0][tid] + s_lpart[1][tid] + s_b2;
            const float beta = 1.f / (1.f + __expf(-logit));
            const int grow = tile * TILE_M + tid;
            const int ty = __ldg(types + grow);
            const bool car = (ty == 0) && rdmask(masks, grow, mt);
            out[(size_t)NROWS * DDIM + grow] = car ? beta : 0.f;
            s_bb[tid] = car ? beta : 1.f;
            s_rr[tid] = car ? (1.f - beta) : 0.f;
        }
        __syncthreads();

        // ---- epilogue 2: blend from SMEM A tile (exact fp32 h), coalesced stores ----
#pragma unroll
        for (int j = 0; j < 8; j++) {
            const int idx = j * 512 + tid;
            const int row = idx >> 5, q = idx & 31;
            const float4 a = *(const float4*)(A + row * APAD + q * 4);
            const float4 rv = *(const float4*)(s_rule + q * 4);
            const float bbv = s_bb[row], rrv = s_rr[row];
            float4 o;
            o.x = fmaf(bbv, a.x, rrv * rv.x);
            o.y = fmaf(bbv, a.y, rrv * rv.y);
            o.z = fmaf(bbv, a.z, rrv * rv.z);
            o.w = fmaf(bbv, a.w, rrv * rv.w);
            *(float4*)(out + ((size_t)(tile * TILE_M + row)) * DDIM + q * 4) = o;
        }

        buf ^= 1;
    }
}

// ---------------- launch ----------------
extern "C" void kernel_launch(void* const* d_in, const int* in_sizes, int n_in,
                              void* d_out, int out_size) {
    const float* h;
    const int*   types;
    const void*  masks;
    const int*   rid;
    const float* W1; const float* b1; const float* W2; const float* b2; const float* rtab;

    if (n_in >= 9) {
        h = (const float*)d_in[0]; types = (const int*)d_in[1]; masks = d_in[2];
        rid = (const int*)d_in[3];
        W1 = (const float*)d_in[4]; b1 = (const float*)d_in[5];
        W2 = (const float*)d_in[6]; b2 = (const float*)d_in[7];
        rtab = (const float*)d_in[8];
    } else {  // rule_id omitted by harness
        h = (const float*)d_in[0]; types = (const int*)d_in[1]; masks = d_in[2];
        rid = nullptr;
        W1 = (const float*)d_in[3]; b1 = (const float*)d_in[4];
        W2 = (const float*)d_in[5]; b2 = (const float*)d_in[6];
        rtab = (const float*)d_in[7];
    }
    float* out = (float*)d_out;

    pool1_kernel<<<P1_BLOCKS, 512>>>(h, types, masks);
    setup_kernel<<<17, 512>>>(W1, b1);
    cudaFuncSetAttribute(main_kernel, cudaFuncAttributeMaxDynamicSharedMemorySize, DSMEM_BYTES);
    main_kernel<<<GRID_MAIN, 512, DSMEM_BYTES>>>(h, types, masks, rid, W2, b2, rtab, out);
}

// round 17
// speedup vs baseline: 1.9135x; 1.0007x over previous
#include <cuda_runtime.h>
#include <cstdint>

// ---------------- problem constants ----------------
#define NROWS   262144
#define DDIM    128
#define TILE_M  128
#define NTILES  (NROWS / TILE_M)        // 2048
#define GRID_MAIN 148
#define P1_BLOCKS 512
#define P1_RPB  (NROWS / P1_BLOCKS)     // 512 rows per block (16 warps x 32 rows)

#define APAD 132                        // floats per padded A row
#define ABUF_FLOATS (TILE_M * APAD)     // 16896
#define SB_U32   (8 * 16 * 32 * 2)      // 8192 u32: B fp16 fragments [kk][nblk][lane][e]
#define DSMEM_BYTES (2 * ABUF_FLOATS * 4 + SB_U32 * 4)   // 167936

// ---------------- device scratch (no allocs allowed) ----------------
__device__ float    g_part[P1_BLOCKS * 2 * 128];
__device__ int      g_cnt[P1_BLOCKS * 2];
__device__ float    g_bias[128];
__device__ uint32_t g_Bperm[SB_U32];

// ---------------- small helpers ----------------
__device__ __forceinline__ uint32_t smem_u32(const void* p) {
    uint32_t r;
    asm("{ .reg .u64 t; cvta.to.shared.u64 t, %1; cvt.u32.u64 %0, t; }" : "=r"(r) : "l"(p));
    return r;
}

__device__ __forceinline__ void cp16(uint32_t dst, const void* src) {
    asm volatile("cp.async.cg.shared.global [%0], [%1], 16;" :: "r"(dst), "l"(src));
}

__device__ __forceinline__ int sniff_mt(const void* m) {
    const int v = *(const int*)m;
    return (v == 0x01010101) ? 1 : ((v == 0x3F800000) ? 2 : 0);
}

__device__ __forceinline__ bool rdmask(const void* m, int i, int mt) {
    if (mt == 1) return ((const unsigned char*)m)[i] != 0;
    if (mt == 2) return ((const float*)m)[i] != 0.0f;
    return ((const int*)m)[i] != 0;
}

// pack two f32 -> f16x2 (lo = first arg)
__device__ __forceinline__ uint32_t pack_h2(float lo, float hi) {
    uint32_t r;
    asm("cvt.rn.f16x2.f32 %0, %1, %2;" : "=r"(r) : "f"(hi), "f"(lo));
    return r;
}

__device__ __forceinline__ void mma_fp16(float* d, uint32_t a0, uint32_t a1,
                                         uint32_t a2, uint32_t a3,
                                         uint32_t b0, uint32_t b1) {
    asm volatile(
        "mma.sync.aligned.m16n8k16.row.col.f32.f16.f16.f32 "
        "{%0,%1,%2,%3}, {%4,%5,%6,%7}, {%8,%9}, {%0,%1,%2,%3};\n"
        : "+f"(d[0]), "+f"(d[1]), "+f"(d[2]), "+f"(d[3])
        : "r"(a0), "r"(a1), "r"(a2), "r"(a3), "r"(b0), "r"(b1));
}

// ---------------- kernel 1: warp-per-row masked partial sums ----------------
// 512 threads = 16 warps; warp handles 32 consecutive rows; lane owns 4 columns.
// Rows with type==0 or mask==0 are skipped entirely (no h load) - warp-uniform branch.
__global__ void __launch_bounds__(512) pool1_kernel(const float* __restrict__ h,
                                                    const int* __restrict__ types,
                                                    const void* __restrict__ masks) {
    __shared__ float s_red[2][16][128];
    __shared__ int   s_cnt[2][16];
    const int tid = threadIdx.x;
    const int warp = tid >> 5, lane = tid & 31;
    const int mt = sniff_mt(masks);
    const int rbase = blockIdx.x * P1_RPB + warp * 32;

    float4 sl = make_float4(0.f, 0.f, 0.f, 0.f);
    float4 ss = make_float4(0.f, 0.f, 0.f, 0.f);
    int cl = 0, cs = 0;

#pragma unroll
    for (int j = 0; j < 32; j += 4) {
        const int i0 = rbase + j;
        const int4 ty4 = *(const int4*)(types + i0);
        int tys[4] = {ty4.x, ty4.y, ty4.z, ty4.w};
        bool ms[4];
        if (mt == 1) {
            const uchar4 mv = *(const uchar4*)((const unsigned char*)masks + i0);
            ms[0] = mv.x != 0; ms[1] = mv.y != 0; ms[2] = mv.z != 0; ms[3] = mv.w != 0;
        } else if (mt == 2) {
            const float4 mv = *(const float4*)((const float*)masks + i0);
            ms[0] = mv.x != 0.f; ms[1] = mv.y != 0.f; ms[2] = mv.z != 0.f; ms[3] = mv.w != 0.f;
        } else {
            const int4 mv = *(const int4*)((const int*)masks + i0);
            ms[0] = mv.x != 0; ms[1] = mv.y != 0; ms[2] = mv.z != 0; ms[3] = mv.w != 0;
        }
#pragma unroll
        for (int u = 0; u < 4; u++) {
            const int ty = tys[u];
            if (ms[u] && ty != 0) {
                const float4 v = *(const float4*)(h + (size_t)(i0 + u) * DDIM + lane * 4);
                if (ty == 1) {
                    sl.x += v.x; sl.y += v.y; sl.z += v.z; sl.w += v.w; cl++;
                } else {
                    ss.x += v.x; ss.y += v.y; ss.z += v.z; ss.w += v.w; cs++;
                }
            }
        }
    }

    *(float4*)&s_red[0][warp][lane * 4] = sl;
    *(float4*)&s_red[1][warp][lane * 4] = ss;
    if (lane == 0) { s_cnt[0][warp] = cl; s_cnt[1][warp] = cs; }
    __syncthreads();

    if (tid < 256) {
        const int which = tid >> 7, col = tid & 127;
        float acc = 0.f;
#pragma unroll
        for (int w = 0; w < 16; w++) acc += s_red[which][w][col];
        g_part[(blockIdx.x * 2 + which) * 128 + col] = acc;
    }
    if (tid < 2) {
        int c = 0;
#pragma unroll
        for (int w = 0; w < 16; w++) c += s_cnt[tid][w];
        g_cnt[blockIdx.x * 2 + tid] = c;
    }
}

// ---------------- kernel 2 (fused): block 0 = pool2 reduce+bias fold;
//                  blocks 1..16 = pre-permute W1a into fp16 B fragments ----------------
// B fragment (m16n8k16 row.col): n = nblk*8 + lane/4, k = kk*16 + 2*(lane%4) + 8*e (+h)
__global__ void __launch_bounds__(512) setup_kernel(const float* __restrict__ W1,
                                                    const float* __restrict__ b1) {
    const int t = threadIdx.x;
    if (blockIdx.x > 0) {
        const int idx = (blockIdx.x - 1) * 512 + t;     // 0 .. 8191
        const int e    = idx & 1;
        const int lane = (idx >> 1) & 31;
        const int nblk = (idx >> 6) & 15;
        const int kk   = idx >> 10;                     // 0..7
        const int n = nblk * 8 + (lane >> 2);
        const int k = kk * 16 + 2 * (lane & 3) + 8 * e;
        const float v0 = __ldg(W1 + (size_t)n * 384 + k);
        const float v1 = __ldg(W1 + (size_t)n * 384 + k + 1);
        g_Bperm[idx] = pack_h2(v0, v1);
        return;
    }
    // ----- block 0: pool2 -----
    __shared__ float s_sl[4][128], s_ss[4][128];
    __shared__ float s_hl[128], s_hs[128];
    __shared__ int s_cl, s_cs;
    const int col = t & 127, p = t >> 7;
    float sl = 0.f, ss = 0.f;
#pragma unroll 4
    for (int g = p * (P1_BLOCKS / 4); g < (p + 1) * (P1_BLOCKS / 4); ++g) {
        sl += g_part[(g * 2 + 0) * 128 + col];
        ss += g_part[(g * 2 + 1) * 128 + col];
    }
    s_sl[p][col] = sl;
    s_ss[p][col] = ss;
    if (t < 32) {
        int cl = 0, cs = 0;
        for (int g = t; g < P1_BLOCKS; g += 32) { cl += g_cnt[g * 2]; cs += g_cnt[g * 2 + 1]; }
#pragma unroll
        for (int o = 16; o > 0; o >>= 1) {
            cl += __shfl_down_sync(0xFFFFFFFFu, cl, o);
            cs += __shfl_down_sync(0xFFFFFFFFu, cs, o);
        }
        if (t == 0) { s_cl = cl; s_cs = cs; }
    }
    __syncthreads();
    if (t < 128) {
        float SL = s_sl[0][t] + s_sl[1][t] + s_sl[2][t] + s_sl[3][t];
        float SS = s_ss[0][t] + s_ss[1][t] + s_ss[2][t] + s_ss[3][t];
        s_hl[t] = (s_cl > 0) ? SL / (float)s_cl : 0.f;
        s_hs[t] = (s_cs > 0) ? SS / (float)s_cs : 0.f;
    }
    __syncthreads();
    if (t < 128) {
        float acc = b1[t];
        const float* w = W1 + (size_t)t * 384;
#pragma unroll 8
        for (int k = 0; k < 128; k++)
            acc += w[128 + k] * s_hl[k] + w[256 + k] * s_hs[k];
        g_bias[t] = acc;
    }
}

// ---------------- kernel 3: persistent fp16 mma.sync GEMM + fused epilogue --------
// 512 threads, 16 warps: warpRow = warp>>1 (16 rows), warpCol = warp&1 (64 cols)
__global__ void __launch_bounds__(512, 1)
main_kernel(const float* __restrict__ h, const int* __restrict__ types,
            const void* __restrict__ masks, const int* __restrict__ rid,
            const float* __restrict__ W2, const float* __restrict__ b2,
            const float* __restrict__ rtab, float* __restrict__ out) {
    extern __shared__ float sm[];
    uint32_t* sB = (uint32_t*)(sm + 2 * ABUF_FLOATS);
    __shared__ float s_bias[128], s_w2[128];
    __shared__ __align__(16) float s_rule[128];
    __shared__ float s_bb[128], s_rr[128];
    __shared__ float s_lpart[2][128];
    __shared__ float s_b2;

    const int tid  = threadIdx.x;
    const int warp = tid >> 5;
    const int lane = tid & 31;
    const int warpRow = warp >> 1;      // 0..7
    const int warpCol = warp & 1;       // 0..1
    const int g  = lane >> 2;           // 0..7
    const int t4 = lane & 3;            // 0..3
    const int mt = sniff_mt(masks);
    const uint32_t sAaddr = smem_u32(sm);
    const uint32_t sBaddr = smem_u32(sB);

    if (tid < 128) {
        s_bias[tid] = g_bias[tid];
        s_w2[tid]   = __ldg(W2 + tid);
        const int rv = rid ? __ldg(rid) : 0;
        s_rule[tid] = __ldg(rtab + (size_t)rv * 128 + tid);
    }
    if (tid == 0) s_b2 = __ldg(b2);

    // prologue: cp.async B fragments (32 KB) + first A tile
#pragma unroll
    for (int i = 0; i < 4; i++) {
        const int q = i * 512 + tid;                 // 0..2047 16B quads
        cp16(sBaddr + q * 16, g_Bperm + q * 4);
    }
    {
        const float* src = h + (size_t)blockIdx.x * TILE_M * DDIM;
#pragma unroll
        for (int i = 0; i < 8; i++) {
            const int idx = i * 512 + tid;
            const int row = idx >> 5, q = idx & 31;
            cp16(sAaddr + row * (APAD * 4) + q * 16, src + row * DDIM + q * 4);
        }
    }
    asm volatile("cp.async.commit_group;");

    int buf = 0;
    for (int tile = blockIdx.x; tile < NTILES; tile += GRID_MAIN) {
        asm volatile("cp.async.wait_group 0;" ::: "memory");
        __syncthreads();

        // prefetch next tile into the other buffer
        const int ntile = tile + GRID_MAIN;
        if (ntile < NTILES) {
            const uint32_t dst = sAaddr + (buf ^ 1) * (ABUF_FLOATS * 4);
            const float* src = h + (size_t)ntile * TILE_M * DDIM;
#pragma unroll
            for (int i = 0; i < 8; i++) {
                const int idx = i * 512 + tid;
                const int row = idx >> 5, q = idx & 31;
                cp16(dst + row * (APAD * 4) + q * 16, src + row * DDIM + q * 4);
            }
        }
        asm volatile("cp.async.commit_group;");

        // ---- GEMM: warp owns rows [warpRow*16, +16), cols [warpCol*64, +64) ----
        const float* A = sm + buf * ABUF_FLOATS;
        const float* a0p = A + (warpRow * 16 + g) * APAD + 2 * t4;
        const float* a1p = a0p + 8 * APAD;

        float acc[32];
#pragma unroll
        for (int i = 0; i < 32; i++) acc[i] = 0.f;

#pragma unroll
        for (int kk = 0; kk < 8; kk++) {
            const float2 f0 = *(const float2*)(a0p + kk * 16);
            const float2 f1 = *(const float2*)(a1p + kk * 16);
            const float2 f2 = *(const float2*)(a0p + kk * 16 + 8);
            const float2 f3 = *(const float2*)(a1p + kk * 16 + 8);
            const uint32_t A0 = pack_h2(f0.x, f0.y);
            const uint32_t A1 = pack_h2(f1.x, f1.y);
            const uint32_t A2 = pack_h2(f2.x, f2.y);
            const uint32_t A3 = pack_h2(f3.x, f3.y);
            const uint32_t* bp = sB + ((kk * 16 + warpCol * 8) * 32 + lane) * 2;
#pragma unroll
            for (int nb = 0; nb < 8; nb++) {
                const uint32_t b0 = bp[nb * 64];
                const uint32_t b1 = bp[nb * 64 + 1];
                mma_fp16(acc + nb * 4, A0, A1, A2, A3, b0, b1);
            }
        }

        // ---- epilogue 1: partial beta dot over this warp's 64 cols ----
        float s0 = 0.f, s1 = 0.f;
#pragma unroll
        for (int nb = 0; nb < 8; nb++) {
            const int col0 = warpCol * 64 + nb * 8 + 2 * t4;
            const float w0 = s_w2[col0], w1 = s_w2[col0 + 1];
            const float bb0 = s_bias[col0], bb1 = s_bias[col0 + 1];
            s0 = fmaf(fmaxf(acc[nb * 4 + 0] + bb0, 0.f), w0,
                 fmaf(fmaxf(acc[nb * 4 + 1] + bb1, 0.f), w1, s0));
            s1 = fmaf(fmaxf(acc[nb * 4 + 2] + bb0, 0.f), w0,
                 fmaf(fmaxf(acc[nb * 4 + 3] + bb1, 0.f), w1, s1));
        }
        s0 += __shfl_xor_sync(0xFFFFFFFFu, s0, 1);
        s0 += __shfl_xor_sync(0xFFFFFFFFu, s0, 2);
        s1 += __shfl_xor_sync(0xFFFFFFFFu, s1, 1);
        s1 += __shfl_xor_sync(0xFFFFFFFFu, s1, 2);
        if (t4 == 0) {
            s_lpart[warpCol][warpRow * 16 + g]     = s0;
            s_lpart[warpCol][warpRow * 16 + g + 8] = s1;
        }
        __syncthreads();

        if (tid < 128) {
            const float logit = s_lpart[0][tid] + s_lpart[1][tid] + s_b2;
            const float beta = 1.f / (1.f + __expf(-logit));
            const int grow = tile * TILE_M + tid;
            const int ty = __ldg(types + grow);
            const bool car = (ty == 0) && rdmask(masks, grow, mt);
            out[(size_t)NROWS * DDIM + grow] = car ? beta : 0.f;
            s_bb[tid] = car ? beta : 1.f;
            s_rr[tid] = car ? (1.f - beta) : 0.f;
        }
        __syncthreads();

        // ---- epilogue 2: blend from SMEM A tile (exact fp32 h), coalesced stores ----
#pragma unroll
        for (int j = 0; j < 8; j++) {
            const int idx = j * 512 + tid;
            const int row = idx >> 5, q = idx & 31;
            const float4 a = *(const float4*)(A + row * APAD + q * 4);
            const float4 rv = *(const float4*)(s_rule + q * 4);
            const float bbv = s_bb[row], rrv = s_rr[row];
            float4 o;
            o.x = fmaf(bbv, a.x, rrv * rv.x);
            o.y = fmaf(bbv, a.y, rrv * rv.y);
            o.z = fmaf(bbv, a.z, rrv * rv.z);
            o.w = fmaf(bbv, a.w, rrv * rv.w);
            *(float4*)(out + ((size_t)(tile * TILE_M + row)) * DDIM + q * 4) = o;
        }

        buf ^= 1;
    }
}

// ---------------- launch ----------------
extern "C" void kernel_launch(void* const* d_in, const int* in_sizes, int n_in,
                              void* d_out, int out_size) {
    const float* h;
    const int*   types;
    const void*  masks;
    const int*   rid;
    const float* W1; const float* b1; const float* W2; const float* b2; const float* rtab;

    if (n_in >= 9) {
        h = (const float*)d_in[0]; types = (const int*)d_in[1]; masks = d_in[2];
        rid = (const int*)d_in[3];
        W1 = (const float*)d_in[4]; b1 = (const float*)d_in[5];
        W2 = (const float*)d_in[6]; b2 = (const float*)d_in[7];
        rtab = (const float*)d_in[8];
    } else {  // rule_id omitted by harness
        h = (const float*)d_in[0]; types = (const int*)d_in[1]; masks = d_in[2];
        rid = nullptr;
        W1 = (const float*)d_in[3]; b1 = (const float*)d_in[4];
        W2 = (const float*)d_in[5]; b2 = (const float*)d_in[6];
        rtab = (const float*)d_in[7];
    }
    float* out = (float*)d_out;

    pool1_kernel<<<P1_BLOCKS, 512>>>(h, types, masks);
    setup_kernel<<<17, 512>>>(W1, b1);
    cudaFuncSetAttribute(main_kernel, cudaFuncAttributeMaxDynamicSharedMemorySize, DSMEM_BYTES);
    main_kernel<<<GRID_MAIN, 512, DSMEM_BYTES>>>(h, types, masks, rid, W2, b2, rtab, out);
}